// round 1
// baseline (speedup 1.0000x reference)
#include <cuda_runtime.h>
#include <math.h>

#define N_NODES 50000
#define N_EDGES 400000
#define HEADS 8
#define HID 32
#define F 256            // HEADS*HID
#define NEG 0.2f

// ---------------- scratch (device globals: allocation-free) ----------------
__device__ float    g_h[N_NODES * F];        // X @ W (pre-attention features)
__device__ float    g_agg[N_NODES * F];      // attention-aggregated output
__device__ float    g_x[N_NODES * F];        // relu(agg + b): layer input/output
__device__ float    g_asrc[N_NODES * HEADS];
__device__ float    g_adst[N_NODES * HEADS];
__device__ float    g_eself[N_NODES * HEADS];
__device__ float    g_mf[N_NODES * HEADS];
__device__ float    g_denom[N_NODES * HEADS];
__device__ unsigned g_menc[N_NODES * HEADS];

// monotone float<->uint mapping for atomicMax on floats of either sign
__device__ __forceinline__ unsigned enc_f(float f) {
    unsigned b = __float_as_uint(f);
    return (b & 0x80000000u) ? ~b : (b | 0x80000000u);
}
__device__ __forceinline__ float dec_f(unsigned k) {
    unsigned b = (k & 0x80000000u) ? (k ^ 0x80000000u) : ~k;
    return __uint_as_float(b);
}
__device__ __forceinline__ float leaky(float x) { return x > 0.f ? x : NEG * x; }

// ---------------- SGEMM: C[M x 256] = A[M x K] @ B[K x 256] ----------------
// 128x64 tile, BK=16, 256 threads, 8x4 micro-tile
__global__ __launch_bounds__(256) void sgemm_kernel(
    const float* __restrict__ A, const float* __restrict__ B,
    float* __restrict__ C, int M, int K)
{
    __shared__ float As[16][128];
    __shared__ float Bs[16][64];
    const int tid = threadIdx.x;
    const int tx = tid & 15;        // 16 col groups * 4
    const int ty = tid >> 4;        // 16 row groups * 8
    const int m0 = blockIdx.x * 128;
    const int n0 = blockIdx.y * 64;

    float acc[8][4];
#pragma unroll
    for (int i = 0; i < 8; ++i)
#pragma unroll
        for (int j = 0; j < 4; ++j) acc[i][j] = 0.f;

    for (int k0 = 0; k0 < K; k0 += 16) {
        // A tile: 128x16 = 512 float4
#pragma unroll
        for (int jj = 0; jj < 2; ++jj) {
            int f = tid + jj * 256;
            int m = f >> 2;
            int kq = (f & 3) * 4;
            float4 v = make_float4(0.f, 0.f, 0.f, 0.f);
            if (m0 + m < M)
                v = *(const float4*)&A[(size_t)(m0 + m) * K + k0 + kq];
            As[kq + 0][m] = v.x; As[kq + 1][m] = v.y;
            As[kq + 2][m] = v.z; As[kq + 3][m] = v.w;
        }
        // B tile: 16x64 = 256 float4
        {
            int kk = tid >> 4;
            int nq = (tid & 15) * 4;
            *(float4*)&Bs[kk][nq] = *(const float4*)&B[(size_t)(k0 + kk) * 256 + n0 + nq];
        }
        __syncthreads();
#pragma unroll
        for (int kk = 0; kk < 16; ++kk) {
            float4 b4 = *(float4*)&Bs[kk][tx * 4];
            float4 a0 = *(float4*)&As[kk][ty * 8];
            float4 a1 = *(float4*)&As[kk][ty * 8 + 4];
            float a[8] = {a0.x, a0.y, a0.z, a0.w, a1.x, a1.y, a1.z, a1.w};
#pragma unroll
            for (int i = 0; i < 8; ++i) {
                acc[i][0] += a[i] * b4.x; acc[i][1] += a[i] * b4.y;
                acc[i][2] += a[i] * b4.z; acc[i][3] += a[i] * b4.w;
            }
        }
        __syncthreads();
    }
#pragma unroll
    for (int i = 0; i < 8; ++i) {
        int m = m0 + ty * 8 + i;
        if (m < M)
            *(float4*)&C[(size_t)m * 256 + n0 + tx * 4] =
                make_float4(acc[i][0], acc[i][1], acc[i][2], acc[i][3]);
    }
}

// ---------------- node prep: alpha_src/dst, self-loop init ----------------
// one warp per node
__global__ __launch_bounds__(256) void node_prep_kernel(
    const float* __restrict__ a_src, const float* __restrict__ a_dst)
{
    __shared__ float sA[256], sD[256];
    const int tid = threadIdx.x;
    sA[tid] = a_src[tid];
    sD[tid] = a_dst[tid];
    __syncthreads();
    const int warp = tid >> 5, lane = tid & 31;
    const int n = blockIdx.x * 8 + warp;
    if (n >= N_NODES) return;

    float res_s = 0.f, res_d = 0.f;
#pragma unroll
    for (int h = 0; h < 8; ++h) {
        float v = g_h[(size_t)n * 256 + h * 32 + lane];
        float ps = v * sA[h * 32 + lane];
        float pd = v * sD[h * 32 + lane];
#pragma unroll
        for (int off = 16; off; off >>= 1) {
            ps += __shfl_xor_sync(0xffffffffu, ps, off);
            pd += __shfl_xor_sync(0xffffffffu, pd, off);
        }
        if (lane == h) { res_s = ps; res_d = pd; }
    }
    if (lane < 8) {
        int idx = n * 8 + lane;
        g_asrc[idx] = res_s;
        g_adst[idx] = res_d;
        float e = leaky(res_s + res_d);      // self-loop: src==dst==n
        g_eself[idx] = e;
        g_menc[idx] = enc_f(e);
        g_denom[idx] = 0.f;
    }
}

// ---------------- edge pass 1: segment max ----------------
__global__ __launch_bounds__(256) void edge_max_kernel(const int* __restrict__ ei)
{
    int e = blockIdx.x * blockDim.x + threadIdx.x;
    if (e >= N_EDGES) return;
    int s = ei[e], d = ei[N_EDGES + e];
    float4 s0 = *(const float4*)&g_asrc[s * 8];
    float4 s1 = *(const float4*)&g_asrc[s * 8 + 4];
    float4 d0 = *(const float4*)&g_adst[d * 8];
    float4 d1 = *(const float4*)&g_adst[d * 8 + 4];
    float ev[8] = {s0.x + d0.x, s0.y + d0.y, s0.z + d0.z, s0.w + d0.w,
                   s1.x + d1.x, s1.y + d1.y, s1.z + d1.z, s1.w + d1.w};
#pragma unroll
    for (int h = 0; h < 8; ++h)
        atomicMax(&g_menc[d * 8 + h], enc_f(leaky(ev[h])));
}

// ---------------- node: decode max, seed denom with self term ----------------
__global__ __launch_bounds__(256) void node_fin_kernel()
{
    int i = blockIdx.x * blockDim.x + threadIdx.x;
    if (i >= N_NODES * 8) return;
    float m = dec_f(g_menc[i]);
    g_mf[i] = m;
    g_denom[i] = expf(g_eself[i] - m);
}

// ---------------- edge pass 2: softmax denominator ----------------
__global__ __launch_bounds__(256) void edge_denom_kernel(const int* __restrict__ ei)
{
    int e = blockIdx.x * blockDim.x + threadIdx.x;
    if (e >= N_EDGES) return;
    int s = ei[e], d = ei[N_EDGES + e];
    float4 s0 = *(const float4*)&g_asrc[s * 8];
    float4 s1 = *(const float4*)&g_asrc[s * 8 + 4];
    float4 d0 = *(const float4*)&g_adst[d * 8];
    float4 d1 = *(const float4*)&g_adst[d * 8 + 4];
    float4 m0 = *(const float4*)&g_mf[d * 8];
    float4 m1 = *(const float4*)&g_mf[d * 8 + 4];
    float ev[8] = {s0.x + d0.x, s0.y + d0.y, s0.z + d0.z, s0.w + d0.w,
                   s1.x + d1.x, s1.y + d1.y, s1.z + d1.z, s1.w + d1.w};
    float mm[8] = {m0.x, m0.y, m0.z, m0.w, m1.x, m1.y, m1.z, m1.w};
#pragma unroll
    for (int h = 0; h < 8; ++h)
        atomicAdd(&g_denom[d * 8 + h], expf(leaky(ev[h]) - mm[h]));
}

// ---------------- node: init agg with self-loop message ----------------
// one warp per node
__global__ __launch_bounds__(256) void agg_init_kernel()
{
    const int warp = threadIdx.x >> 5, lane = threadIdx.x & 31;
    const int n = blockIdx.x * 8 + warp;
    if (n >= N_NODES) return;
    float a = 0.f;
    if (lane < 8) {
        int idx = n * 8 + lane;
        a = expf(g_eself[idx] - g_mf[idx]) / g_denom[idx];
    }
    float al0 = __shfl_sync(0xffffffffu, a, lane >> 3);
    float al1 = __shfl_sync(0xffffffffu, a, 4 + (lane >> 3));
    float4 v0 = *(float4*)&g_h[(size_t)n * 256 + lane * 4];
    float4 v1 = *(float4*)&g_h[(size_t)n * 256 + 128 + lane * 4];
    v0.x *= al0; v0.y *= al0; v0.z *= al0; v0.w *= al0;
    v1.x *= al1; v1.y *= al1; v1.z *= al1; v1.w *= al1;
    *(float4*)&g_agg[(size_t)n * 256 + lane * 4] = v0;
    *(float4*)&g_agg[(size_t)n * 256 + 128 + lane * 4] = v1;
}

// ---------------- edge pass 3: weighted aggregation (one warp / edge) ------
__global__ __launch_bounds__(256) void edge_agg_kernel(const int* __restrict__ ei)
{
    const int warp = threadIdx.x >> 5, lane = threadIdx.x & 31;
    const int e = blockIdx.x * 8 + warp;
    if (e >= N_EDGES) return;
    int s = ei[e], d = ei[N_EDGES + e];
    float a = 0.f;
    if (lane < 8) {
        float ee = leaky(g_asrc[s * 8 + lane] + g_adst[d * 8 + lane]);
        a = expf(ee - g_mf[d * 8 + lane]) / g_denom[d * 8 + lane];
    }
    float al0 = __shfl_sync(0xffffffffu, a, lane >> 3);
    float al1 = __shfl_sync(0xffffffffu, a, 4 + (lane >> 3));
    float4 v0 = *(const float4*)&g_h[(size_t)s * 256 + lane * 4];
    float4 v1 = *(const float4*)&g_h[(size_t)s * 256 + 128 + lane * 4];
    v0.x *= al0; v0.y *= al0; v0.z *= al0; v0.w *= al0;
    v1.x *= al1; v1.y *= al1; v1.z *= al1; v1.w *= al1;
    atomicAdd((float4*)&g_agg[(size_t)d * 256 + lane * 4], v0);
    atomicAdd((float4*)&g_agg[(size_t)d * 256 + 128 + lane * 4], v1);
}

// ---------------- node: x = relu(agg + b) ----------------
__global__ __launch_bounds__(256) void node_out_kernel(const float* __restrict__ b)
{
    int i = blockIdx.x * blockDim.x + threadIdx.x;      // float4 index
    if (i >= N_NODES * F / 4) return;
    float4 v = *(float4*)&g_agg[(size_t)i * 4];
    int c = (i * 4) & 255;
    float4 bb = *(const float4*)&b[c];
    v.x += bb.x; v.y += bb.y; v.z += bb.z; v.w += bb.w;
    v.x = v.x > 0.f ? v.x : 0.f;
    v.y = v.y > 0.f ? v.y : 0.f;
    v.z = v.z > 0.f ? v.z : 0.f;
    v.w = v.w > 0.f ? v.w : 0.f;
    *(float4*)&g_x[(size_t)i * 4] = v;
}

// ---------------- fused edge-MLP + predictor ----------------
// 64 edges per block, 128 threads, 4 edges x 4 cols per thread.
// ef = [x2[row] (256) | x2[col] (256) | emb (32)], Wp1 streamed in 64-row chunks.
__global__ __launch_bounds__(128) void mlp_pred_kernel(
    const int* __restrict__ ei, const float* __restrict__ edge_attr,
    const float* __restrict__ x2,
    const float* __restrict__ Wm1, const float* __restrict__ bm1,
    const float* __restrict__ Wm2, const float* __restrict__ bm2,
    const float* __restrict__ Wp1, const float* __restrict__ bp1,
    const float* __restrict__ Wp2, const float* __restrict__ bp2,
    float* __restrict__ out)
{
    __shared__ float sU[64 * 66];      // sEF[64][66] / {sEA[64][33], sT1[64][33]}
    __shared__ float sEMB[64 * 33];
    __shared__ float sW[2048];         // Wp1 chunk [64][32] / {Wm1, Wm2}
    __shared__ int   sRow[64], sCol[64];
    __shared__ float sB[64];           // bm1 | bm2

    const int tid = threadIdx.x;
    const int tx = tid & 7;            // col group (cols tx*4..tx*4+3)
    const int ey = tid >> 3;           // edge group (edges ey*4..ey*4+3)
    const int e0 = blockIdx.x * 64;

    if (tid < 64) {
        sRow[tid] = ei[e0 + tid];
        sCol[tid] = ei[N_EDGES + e0 + tid];
    }
    for (int i = tid; i < 2048; i += 128)
        sW[i] = (i < 1024) ? Wm1[i] : Wm2[i - 1024];
    if (tid < 32) { sB[tid] = bm1[tid]; sB[32 + tid] = bm2[tid]; }

    float* sEA = sU;
    float* sT1 = sU + 64 * 33;
    for (int f = tid; f < 64 * 8; f += 128) {      // EA: 512 float4
        int e = f >> 3, q = f & 7;
        float4 v = *(const float4*)&edge_attr[(size_t)(e0 + e) * 32 + q * 4];
        float* p = &sEA[e * 33 + q * 4];
        p[0] = v.x; p[1] = v.y; p[2] = v.z; p[3] = v.w;
    }
    __syncthreads();

    // MLP layer 1: T1 = relu(EA @ Wm1 + bm1)
    {
        float acc[4][4];
#pragma unroll
        for (int i = 0; i < 4; ++i)
#pragma unroll
            for (int j = 0; j < 4; ++j) acc[i][j] = 0.f;
#pragma unroll
        for (int k = 0; k < 32; ++k) {
            float4 w = *(const float4*)&sW[k * 32 + tx * 4];
#pragma unroll
            for (int i = 0; i < 4; ++i) {
                float a = sEA[(ey * 4 + i) * 33 + k];
                acc[i][0] += a * w.x; acc[i][1] += a * w.y;
                acc[i][2] += a * w.z; acc[i][3] += a * w.w;
            }
        }
#pragma unroll
        for (int i = 0; i < 4; ++i)
#pragma unroll
            for (int j = 0; j < 4; ++j) {
                float v = acc[i][j] + sB[tx * 4 + j];
                sT1[(ey * 4 + i) * 33 + tx * 4 + j] = v > 0.f ? v : 0.f;
            }
    }
    __syncthreads();
    // MLP layer 2: EMB = relu(T1 @ Wm2 + bm2)
    {
        float acc[4][4];
#pragma unroll
        for (int i = 0; i < 4; ++i)
#pragma unroll
            for (int j = 0; j < 4; ++j) acc[i][j] = 0.f;
#pragma unroll
        for (int k = 0; k < 32; ++k) {
            float4 w = *(const float4*)&sW[1024 + k * 32 + tx * 4];
#pragma unroll
            for (int i = 0; i < 4; ++i) {
                float a = sT1[(ey * 4 + i) * 33 + k];
                acc[i][0] += a * w.x; acc[i][1] += a * w.y;
                acc[i][2] += a * w.z; acc[i][3] += a * w.w;
            }
        }
#pragma unroll
        for (int i = 0; i < 4; ++i)
#pragma unroll
            for (int j = 0; j < 4; ++j) {
                float v = acc[i][j] + sB[32 + tx * 4 + j];
                sEMB[(ey * 4 + i) * 33 + tx * 4 + j] = v > 0.f ? v : 0.f;
            }
    }

    // predictor: acc = EF @ Wp1 over 8 chunks of 64 (x_row, x_col) + 32 (emb)
    float acc[4][4];
#pragma unroll
    for (int i = 0; i < 4; ++i)
#pragma unroll
        for (int j = 0; j < 4; ++j) acc[i][j] = 0.f;

    float* sEF = sU;   // pad 66
    for (int ch = 0; ch < 8; ++ch) {
        __syncthreads();
        for (int i = tid; i < 2048; i += 128) sW[i] = Wp1[ch * 2048 + i];
        for (int f = tid; f < 64 * 16; f += 128) {
            int e = f >> 4, q = f & 15;
            int node = (ch < 4) ? sRow[e] : sCol[e];
            int koff = (ch & 3) * 64;
            float4 v = *(const float4*)&x2[(size_t)node * 256 + koff + q * 4];
            float* p = &sEF[e * 66 + q * 4];
            p[0] = v.x; p[1] = v.y; p[2] = v.z; p[3] = v.w;
        }
        __syncthreads();
#pragma unroll
        for (int k = 0; k < 64; ++k) {
            float4 w = *(const float4*)&sW[k * 32 + tx * 4];
#pragma unroll
            for (int i = 0; i < 4; ++i) {
                float a = sEF[(ey * 4 + i) * 66 + k];
                acc[i][0] += a * w.x; acc[i][1] += a * w.y;
                acc[i][2] += a * w.z; acc[i][3] += a * w.w;
            }
        }
    }
    __syncthreads();
    for (int i = tid; i < 1024; i += 128) sW[i] = Wp1[512 * 32 + i];
    __syncthreads();
#pragma unroll
    for (int k = 0; k < 32; ++k) {
        float4 w = *(const float4*)&sW[k * 32 + tx * 4];
#pragma unroll
        for (int i = 0; i < 4; ++i) {
            float a = sEMB[(ey * 4 + i) * 33 + k];
            acc[i][0] += a * w.x; acc[i][1] += a * w.y;
            acc[i][2] += a * w.z; acc[i][3] += a * w.w;
        }
    }

    // epilogue: out = relu(acc + bp1) @ Wp2 + bp2, reduce across tx (width 8)
    float4 bp = *(const float4*)&bp1[tx * 4];
    float4 wp = *(const float4*)&Wp2[tx * 4];
    float bias2 = bp2[0];
#pragma unroll
    for (int i = 0; i < 4; ++i) {
        float h0 = acc[i][0] + bp.x; h0 = h0 > 0.f ? h0 : 0.f;
        float h1 = acc[i][1] + bp.y; h1 = h1 > 0.f ? h1 : 0.f;
        float h2 = acc[i][2] + bp.z; h2 = h2 > 0.f ? h2 : 0.f;
        float h3 = acc[i][3] + bp.w; h3 = h3 > 0.f ? h3 : 0.f;
        float p = h0 * wp.x + h1 * wp.y + h2 * wp.z + h3 * wp.w;
        p += __shfl_down_sync(0xffffffffu, p, 4, 8);
        p += __shfl_down_sync(0xffffffffu, p, 2, 8);
        p += __shfl_down_sync(0xffffffffu, p, 1, 8);
        if (tx == 0) out[e0 + ey * 4 + i] = p + bias2;
    }
}

// ---------------- host ----------------
extern "C" void kernel_launch(void* const* d_in, const int* in_sizes, int n_in,
                              void* d_out, int out_size)
{
    const float* x   = (const float*)d_in[0];
    const int*   ei  = (const int*)d_in[1];
    const float* ea  = (const float*)d_in[2];
    const float* W1  = (const float*)d_in[3];
    const float* as1 = (const float*)d_in[4];
    const float* ad1 = (const float*)d_in[5];
    const float* b1  = (const float*)d_in[6];
    const float* W2  = (const float*)d_in[7];
    const float* as2 = (const float*)d_in[8];
    const float* ad2 = (const float*)d_in[9];
    const float* b2  = (const float*)d_in[10];
    const float* Wm1 = (const float*)d_in[11];
    const float* bm1 = (const float*)d_in[12];
    const float* Wm2 = (const float*)d_in[13];
    const float* bm2 = (const float*)d_in[14];
    const float* Wp1 = (const float*)d_in[15];
    const float* bp1 = (const float*)d_in[16];
    const float* Wp2 = (const float*)d_in[17];
    const float* bp2 = (const float*)d_in[18];
    float* out = (float*)d_out;

    float *ph = nullptr, *px = nullptr;
    cudaGetSymbolAddress((void**)&ph, g_h);
    cudaGetSymbolAddress((void**)&px, g_x);

    const dim3 gemm_grid(391, 4);     // ceil(50000/128) x (256/64)
    const int EB = (N_EDGES + 255) / 256;            // 1563
    const int NHB = (N_NODES * 8 + 255) / 256;       // 1563
    const int NWB = (N_NODES + 7) / 8;               // 6250 (warp/node)
    const int EWB = (N_EDGES + 7) / 8;               // 50000 (warp/edge)
    const int XOB = (N_NODES * F / 4 + 255) / 256;   // 12500

    for (int layer = 0; layer < 2; ++layer) {
        const float* X   = layer ? px : x;
        const int    K   = layer ? 256 : 128;
        const float* W   = layer ? W2 : W1;
        const float* as_ = layer ? as2 : as1;
        const float* ad_ = layer ? ad2 : ad1;
        const float* b_  = layer ? b2 : b1;

        sgemm_kernel<<<gemm_grid, 256>>>(X, W, ph, N_NODES, K);
        node_prep_kernel<<<NWB, 256>>>(as_, ad_);
        edge_max_kernel<<<EB, 256>>>(ei);
        node_fin_kernel<<<NHB, 256>>>();
        edge_denom_kernel<<<EB, 256>>>(ei);
        agg_init_kernel<<<NWB, 256>>>();
        edge_agg_kernel<<<EWB, 256>>>(ei);
        node_out_kernel<<<XOB, 256>>>(b_);
    }
    mlp_pred_kernel<<<N_EDGES / 64, 128>>>(ei, ea, px,
                                           Wm1, bm1, Wm2, bm2,
                                           Wp1, bp1, Wp2, bp2, out);
}

// round 2
// speedup vs baseline: 1.0972x; 1.0972x over previous
#include <cuda_runtime.h>
#include <math.h>

#define N_NODES 50000
#define N_EDGES 400000
#define HEADS 8
#define HID 32
#define F 256            // HEADS*HID
#define NEG 0.2f

// ---------------- scratch (device globals: allocation-free) ----------------
__device__ float    g_h[N_NODES * F];        // X @ W (pre-attention features)
__device__ float    g_agg[N_NODES * F];      // unnormalized weighted sum
__device__ float    g_x[N_NODES * F];        // relu(agg/denom + b)
__device__ float    g_asrc[N_NODES * HEADS];
__device__ float    g_adst[N_NODES * HEADS];
__device__ float    g_denom[N_NODES * HEADS];

__device__ __forceinline__ float leaky(float x) { return x > 0.f ? x : NEG * x; }

__device__ __forceinline__ unsigned f2tf(float f) {
    unsigned r;
    asm("cvt.rna.tf32.f32 %0, %1;" : "=r"(r) : "f"(f));
    return r;
}

__device__ __forceinline__ void mma8(float* c,
    unsigned a0, unsigned a1, unsigned a2, unsigned a3,
    unsigned b0, unsigned b1)
{
    asm volatile(
        "mma.sync.aligned.m16n8k8.row.col.f32.tf32.tf32.f32 "
        "{%0,%1,%2,%3}, {%4,%5,%6,%7}, {%8,%9}, {%0,%1,%2,%3};"
        : "+f"(c[0]), "+f"(c[1]), "+f"(c[2]), "+f"(c[3])
        : "r"(a0), "r"(a1), "r"(a2), "r"(a3), "r"(b0), "r"(b1));
}

// ---------------- SGEMM: C[M x 256] = A[M x K] @ B[K x 256] ----------------
__global__ __launch_bounds__(256) void sgemm_kernel(
    const float* __restrict__ A, const float* __restrict__ B,
    float* __restrict__ C, int M, int K)
{
    __shared__ float As[16][128];
    __shared__ float Bs[16][64];
    const int tid = threadIdx.x;
    const int tx = tid & 15;
    const int ty = tid >> 4;
    const int m0 = blockIdx.x * 128;
    const int n0 = blockIdx.y * 64;

    float acc[8][4];
#pragma unroll
    for (int i = 0; i < 8; ++i)
#pragma unroll
        for (int j = 0; j < 4; ++j) acc[i][j] = 0.f;

    for (int k0 = 0; k0 < K; k0 += 16) {
#pragma unroll
        for (int jj = 0; jj < 2; ++jj) {
            int f = tid + jj * 256;
            int m = f >> 2;
            int kq = (f & 3) * 4;
            float4 v = make_float4(0.f, 0.f, 0.f, 0.f);
            if (m0 + m < M)
                v = *(const float4*)&A[(size_t)(m0 + m) * K + k0 + kq];
            As[kq + 0][m] = v.x; As[kq + 1][m] = v.y;
            As[kq + 2][m] = v.z; As[kq + 3][m] = v.w;
        }
        {
            int kk = tid >> 4;
            int nq = (tid & 15) * 4;
            *(float4*)&Bs[kk][nq] = *(const float4*)&B[(size_t)(k0 + kk) * 256 + n0 + nq];
        }
        __syncthreads();
#pragma unroll
        for (int kk = 0; kk < 16; ++kk) {
            float4 b4 = *(float4*)&Bs[kk][tx * 4];
            float4 a0 = *(float4*)&As[kk][ty * 8];
            float4 a1 = *(float4*)&As[kk][ty * 8 + 4];
            float a[8] = {a0.x, a0.y, a0.z, a0.w, a1.x, a1.y, a1.z, a1.w};
#pragma unroll
            for (int i = 0; i < 8; ++i) {
                acc[i][0] += a[i] * b4.x; acc[i][1] += a[i] * b4.y;
                acc[i][2] += a[i] * b4.z; acc[i][3] += a[i] * b4.w;
            }
        }
        __syncthreads();
    }
#pragma unroll
    for (int i = 0; i < 8; ++i) {
        int m = m0 + ty * 8 + i;
        if (m < M)
            *(float4*)&C[(size_t)m * 256 + n0 + tx * 4] =
                make_float4(acc[i][0], acc[i][1], acc[i][2], acc[i][3]);
    }
}

// ------- node prep: alpha_src/dst + self-loop weight + agg/denom init ------
// one warp per node
__global__ __launch_bounds__(256) void node_prep_kernel(
    const float* __restrict__ a_src, const float* __restrict__ a_dst)
{
    __shared__ float sA[256], sD[256];
    const int tid = threadIdx.x;
    sA[tid] = a_src[tid];
    sD[tid] = a_dst[tid];
    __syncthreads();
    const int warp = tid >> 5, lane = tid & 31;
    const int n = blockIdx.x * 8 + warp;
    if (n >= N_NODES) return;

    float res_s = 0.f, res_d = 0.f;
#pragma unroll
    for (int h = 0; h < 8; ++h) {
        float v = g_h[(size_t)n * 256 + h * 32 + lane];
        float ps = v * sA[h * 32 + lane];
        float pd = v * sD[h * 32 + lane];
#pragma unroll
        for (int off = 16; off; off >>= 1) {
            ps += __shfl_xor_sync(0xffffffffu, ps, off);
            pd += __shfl_xor_sync(0xffffffffu, pd, off);
        }
        if (lane == h) { res_s = ps; res_d = pd; }
    }
    float w = 0.f;
    if (lane < 8) {
        int idx = n * 8 + lane;
        g_asrc[idx] = res_s;
        g_adst[idx] = res_d;
        w = expf(leaky(res_s + res_d));     // self-loop weight (no max shift)
        g_denom[idx] = w;
    }
    float al0 = __shfl_sync(0xffffffffu, w, lane >> 3);
    float al1 = __shfl_sync(0xffffffffu, w, 4 + (lane >> 3));
    float4 v0 = *(float4*)&g_h[(size_t)n * 256 + lane * 4];
    float4 v1 = *(float4*)&g_h[(size_t)n * 256 + 128 + lane * 4];
    v0.x *= al0; v0.y *= al0; v0.z *= al0; v0.w *= al0;
    v1.x *= al1; v1.y *= al1; v1.z *= al1; v1.w *= al1;
    *(float4*)&g_agg[(size_t)n * 256 + lane * 4] = v0;
    *(float4*)&g_agg[(size_t)n * 256 + 128 + lane * 4] = v1;
}

// ---- single fused edge pass: denom += exp(e), agg += exp(e)*h[src] --------
// one warp per edge
__global__ __launch_bounds__(256) void edge_agg_kernel(const int* __restrict__ ei)
{
    const int warp = threadIdx.x >> 5, lane = threadIdx.x & 31;
    const int e = blockIdx.x * 8 + warp;
    if (e >= N_EDGES) return;
    int s = ei[e], d = ei[N_EDGES + e];
    float w = 0.f;
    if (lane < 8) {
        float ee = leaky(g_asrc[s * 8 + lane] + g_adst[d * 8 + lane]);
        w = expf(ee);
        atomicAdd(&g_denom[d * 8 + lane], w);
    }
    float al0 = __shfl_sync(0xffffffffu, w, lane >> 3);
    float al1 = __shfl_sync(0xffffffffu, w, 4 + (lane >> 3));
    float4 v0 = *(const float4*)&g_h[(size_t)s * 256 + lane * 4];
    float4 v1 = *(const float4*)&g_h[(size_t)s * 256 + 128 + lane * 4];
    v0.x *= al0; v0.y *= al0; v0.z *= al0; v0.w *= al0;
    v1.x *= al1; v1.y *= al1; v1.z *= al1; v1.w *= al1;
    atomicAdd((float4*)&g_agg[(size_t)d * 256 + lane * 4], v0);
    atomicAdd((float4*)&g_agg[(size_t)d * 256 + 128 + lane * 4], v1);
}

// ---------------- node: x = relu(agg/denom + b) ----------------
__global__ __launch_bounds__(256) void node_out_kernel(const float* __restrict__ b)
{
    int i = blockIdx.x * blockDim.x + threadIdx.x;      // float4 index
    if (i >= N_NODES * F / 4) return;
    int n = i >> 6;
    int c4 = i & 63;                    // float4-col within row
    int head = c4 >> 3;
    float inv = 1.f / g_denom[n * 8 + head];
    float4 v = *(float4*)&g_agg[(size_t)i * 4];
    float4 bb = *(const float4*)&b[c4 * 4];
    v.x = v.x * inv + bb.x;
    v.y = v.y * inv + bb.y;
    v.z = v.z * inv + bb.z;
    v.w = v.w * inv + bb.w;
    v.x = v.x > 0.f ? v.x : 0.f;
    v.y = v.y > 0.f ? v.y : 0.f;
    v.z = v.z > 0.f ? v.z : 0.f;
    v.w = v.w > 0.f ? v.w : 0.f;
    *(float4*)&g_x[(size_t)i * 4] = v;
}

// ---------------- fused edge-MLP + predictor (tf32 tensor cores) -----------
// 64 edges per block, 128 threads (4 warps), warp handles 16 rows (m16).
// ef = [x2[row] (256) | x2[col] (256) | emb (32)]  (K = 544), N = 32.
__global__ __launch_bounds__(128) void mlp_pred_tc(
    const int* __restrict__ ei, const float* __restrict__ edge_attr,
    const float* __restrict__ x2,
    const float* __restrict__ Wm1, const float* __restrict__ bm1,
    const float* __restrict__ Wm2, const float* __restrict__ bm2,
    const float* __restrict__ Wp1, const float* __restrict__ bp1,
    const float* __restrict__ Wp2, const float* __restrict__ bp2,
    float* __restrict__ out)
{
    __shared__ unsigned sA[64 * 68];                  // A chunk tf32 [64][68]
    __shared__ __align__(8) unsigned sWp[2112];       // packed W pairs [32][33] x uint2
    __shared__ unsigned sEMB[64 * 33];                // T1 staging (tf32)
    __shared__ unsigned sT[64 * 33];                  // EA -> final emb (tf32)
    __shared__ int sRow[64], sCol[64];

    const int tid = threadIdx.x;
    const int lane = tid & 31;
    const int wrp = tid >> 5;                          // 0..3 -> rows wrp*16..+15
    const int tig = lane & 3;                          // thread-in-group
    const int grp = lane >> 2;                         // group 0..7
    const int e0 = blockIdx.x * 64;

    if (tid < 64) {
        sRow[tid] = ei[e0 + tid];
        sCol[tid] = ei[N_EDGES + e0 + tid];
    }

    // ---- load EA (tf32) + pack Wm1 ----
    for (int f = tid; f < 64 * 8; f += 128) {
        int e = f >> 3, q = f & 7;
        float4 v = *(const float4*)&edge_attr[(size_t)(e0 + e) * 32 + q * 4];
        unsigned* p = &sT[e * 33 + q * 4];
        p[0] = f2tf(v.x); p[1] = f2tf(v.y); p[2] = f2tf(v.z); p[3] = f2tf(v.w);
    }
    for (int i = tid; i < 32 * 32; i += 128) {         // pack Wm1 rows 0..31
        int r = i >> 5, c = i & 31;
        int ks = r >> 3, kk = r & 7;
        sWp[(((ks * 4) + (kk & 3)) * 33 + c) * 2 + (kk >> 2)] = f2tf(Wm1[i]);
    }
    __syncthreads();

    const int row0 = wrp * 16 + grp;

    // ---- edge-MLP layer 1: T1 = relu(EA @ Wm1 + bm1) ----
    {
        float em[4][4];
#pragma unroll
        for (int nt = 0; nt < 4; ++nt)
#pragma unroll
            for (int j = 0; j < 4; ++j) em[nt][j] = 0.f;
#pragma unroll
        for (int ks = 0; ks < 4; ++ks) {
            int k = ks * 8 + tig;
            unsigned a0 = sT[row0 * 33 + k];
            unsigned a1 = sT[(row0 + 8) * 33 + k];
            unsigned a2 = sT[row0 * 33 + k + 4];
            unsigned a3 = sT[(row0 + 8) * 33 + k + 4];
#pragma unroll
            for (int nt = 0; nt < 4; ++nt) {
                uint2 b = *(uint2*)&sWp[((ks * 4 + tig) * 33 + nt * 8 + grp) * 2];
                mma8(em[nt], a0, a1, a2, a3, b.x, b.y);
            }
        }
        __syncthreads();
#pragma unroll
        for (int nt = 0; nt < 4; ++nt) {
            int j0 = nt * 8 + 2 * tig, j1 = j0 + 1;
            float b0 = bm1[j0], b1 = bm1[j1];
            float v;
            v = em[nt][0] + b0; sEMB[row0 * 33 + j0]       = f2tf(v > 0.f ? v : 0.f);
            v = em[nt][1] + b1; sEMB[row0 * 33 + j1]       = f2tf(v > 0.f ? v : 0.f);
            v = em[nt][2] + b0; sEMB[(row0 + 8) * 33 + j0] = f2tf(v > 0.f ? v : 0.f);
            v = em[nt][3] + b1; sEMB[(row0 + 8) * 33 + j1] = f2tf(v > 0.f ? v : 0.f);
        }
    }
    __syncthreads();
    for (int i = tid; i < 32 * 32; i += 128) {         // pack Wm2
        int r = i >> 5, c = i & 31;
        int ks = r >> 3, kk = r & 7;
        sWp[(((ks * 4) + (kk & 3)) * 33 + c) * 2 + (kk >> 2)] = f2tf(Wm2[i]);
    }
    __syncthreads();

    // ---- edge-MLP layer 2: EMB = relu(T1 @ Wm2 + bm2) -> sT ----
    {
        float em[4][4];
#pragma unroll
        for (int nt = 0; nt < 4; ++nt)
#pragma unroll
            for (int j = 0; j < 4; ++j) em[nt][j] = 0.f;
#pragma unroll
        for (int ks = 0; ks < 4; ++ks) {
            int k = ks * 8 + tig;
            unsigned a0 = sEMB[row0 * 33 + k];
            unsigned a1 = sEMB[(row0 + 8) * 33 + k];
            unsigned a2 = sEMB[row0 * 33 + k + 4];
            unsigned a3 = sEMB[(row0 + 8) * 33 + k + 4];
#pragma unroll
            for (int nt = 0; nt < 4; ++nt) {
                uint2 b = *(uint2*)&sWp[((ks * 4 + tig) * 33 + nt * 8 + grp) * 2];
                mma8(em[nt], a0, a1, a2, a3, b.x, b.y);
            }
        }
        __syncthreads();
#pragma unroll
        for (int nt = 0; nt < 4; ++nt) {
            int j0 = nt * 8 + 2 * tig, j1 = j0 + 1;
            float b0 = bm2[j0], b1 = bm2[j1];
            float v;
            v = em[nt][0] + b0; sT[row0 * 33 + j0]       = f2tf(v > 0.f ? v : 0.f);
            v = em[nt][1] + b1; sT[row0 * 33 + j1]       = f2tf(v > 0.f ? v : 0.f);
            v = em[nt][2] + b0; sT[(row0 + 8) * 33 + j0] = f2tf(v > 0.f ? v : 0.f);
            v = em[nt][3] + b1; sT[(row0 + 8) * 33 + j1] = f2tf(v > 0.f ? v : 0.f);
        }
    }

    // ---- predictor: P = EF @ Wp1 over 8 chunks of 64 K + 32 emb K ----
    float p[4][4];
#pragma unroll
    for (int nt = 0; nt < 4; ++nt)
#pragma unroll
        for (int j = 0; j < 4; ++j) p[nt][j] = 0.f;

    for (int ch = 0; ch < 8; ++ch) {
        __syncthreads();
        for (int f = tid; f < 64 * 16; f += 128) {      // gather A chunk
            int e = f >> 4, q = f & 15;
            int node = (ch < 4) ? sRow[e] : sCol[e];
            float4 v = *(const float4*)&x2[(size_t)node * 256 + (ch & 3) * 64 + q * 4];
            unsigned* pp = &sA[e * 68 + q * 4];
            pp[0] = f2tf(v.x); pp[1] = f2tf(v.y); pp[2] = f2tf(v.z); pp[3] = f2tf(v.w);
        }
        for (int i = tid; i < 64 * 32; i += 128) {      // pack Wp1 chunk
            int r = i >> 5, c = i & 31;
            int ks = r >> 3, kk = r & 7;
            sWp[(((ks * 4) + (kk & 3)) * 33 + c) * 2 + (kk >> 2)] = f2tf(Wp1[ch * 2048 + i]);
        }
        __syncthreads();
#pragma unroll
        for (int ks = 0; ks < 8; ++ks) {
            int k = ks * 8 + tig;
            unsigned a0 = sA[row0 * 68 + k];
            unsigned a1 = sA[(row0 + 8) * 68 + k];
            unsigned a2 = sA[row0 * 68 + k + 4];
            unsigned a3 = sA[(row0 + 8) * 68 + k + 4];
#pragma unroll
            for (int nt = 0; nt < 4; ++nt) {
                uint2 b = *(uint2*)&sWp[((ks * 4 + tig) * 33 + nt * 8 + grp) * 2];
                mma8(p[nt], a0, a1, a2, a3, b.x, b.y);
            }
        }
    }
    // emb chunk (K = 32)
    __syncthreads();
    for (int i = tid; i < 32 * 32; i += 128) {          // pack Wp1 rows 512..543
        int r = i >> 5, c = i & 31;
        int ks = r >> 3, kk = r & 7;
        sWp[(((ks * 4) + (kk & 3)) * 33 + c) * 2 + (kk >> 2)] = f2tf(Wp1[512 * 32 + i]);
    }
    __syncthreads();
#pragma unroll
    for (int ks = 0; ks < 4; ++ks) {
        int k = ks * 8 + tig;
        unsigned a0 = sT[row0 * 33 + k];
        unsigned a1 = sT[(row0 + 8) * 33 + k];
        unsigned a2 = sT[row0 * 33 + k + 4];
        unsigned a3 = sT[(row0 + 8) * 33 + k + 4];
#pragma unroll
        for (int nt = 0; nt < 4; ++nt) {
            uint2 b = *(uint2*)&sWp[((ks * 4 + tig) * 33 + nt * 8 + grp) * 2];
            mma8(p[nt], a0, a1, a2, a3, b.x, b.y);
        }
    }

    // ---- epilogue: out = relu(P + bp1) @ Wp2 + bp2 ----
    float r0 = 0.f, r1 = 0.f;
#pragma unroll
    for (int nt = 0; nt < 4; ++nt) {
        int j0 = nt * 8 + 2 * tig, j1 = j0 + 1;
        float b0 = bp1[j0], b1 = bp1[j1];
        float w0 = Wp2[j0], w1 = Wp2[j1];
        float h;
        h = p[nt][0] + b0; r0 += (h > 0.f ? h : 0.f) * w0;
        h = p[nt][1] + b1; r0 += (h > 0.f ? h : 0.f) * w1;
        h = p[nt][2] + b0; r1 += (h > 0.f ? h : 0.f) * w0;
        h = p[nt][3] + b1; r1 += (h > 0.f ? h : 0.f) * w1;
    }
    r0 += __shfl_xor_sync(0xffffffffu, r0, 1);
    r0 += __shfl_xor_sync(0xffffffffu, r0, 2);
    r1 += __shfl_xor_sync(0xffffffffu, r1, 1);
    r1 += __shfl_xor_sync(0xffffffffu, r1, 2);
    if (tig == 0) {
        float bias2 = bp2[0];
        out[e0 + wrp * 16 + grp]     = r0 + bias2;
        out[e0 + wrp * 16 + grp + 8] = r1 + bias2;
    }
}

// ---------------- host ----------------
extern "C" void kernel_launch(void* const* d_in, const int* in_sizes, int n_in,
                              void* d_out, int out_size)
{
    const float* x   = (const float*)d_in[0];
    const int*   ei  = (const int*)d_in[1];
    const float* ea  = (const float*)d_in[2];
    const float* W1  = (const float*)d_in[3];
    const float* as1 = (const float*)d_in[4];
    const float* ad1 = (const float*)d_in[5];
    const float* b1  = (const float*)d_in[6];
    const float* W2  = (const float*)d_in[7];
    const float* as2 = (const float*)d_in[8];
    const float* ad2 = (const float*)d_in[9];
    const float* b2  = (const float*)d_in[10];
    const float* Wm1 = (const float*)d_in[11];
    const float* bm1 = (const float*)d_in[12];
    const float* Wm2 = (const float*)d_in[13];
    const float* bm2 = (const float*)d_in[14];
    const float* Wp1 = (const float*)d_in[15];
    const float* bp1 = (const float*)d_in[16];
    const float* Wp2 = (const float*)d_in[17];
    const float* bp2 = (const float*)d_in[18];
    float* out = (float*)d_out;

    float *ph = nullptr, *px = nullptr;
    cudaGetSymbolAddress((void**)&ph, g_h);
    cudaGetSymbolAddress((void**)&px, g_x);

    const dim3 gemm_grid(391, 4);
    const int NWB = (N_NODES + 7) / 8;               // 6250 (warp/node)
    const int EWB = (N_EDGES + 7) / 8;               // 50000 (warp/edge)
    const int XOB = (N_NODES * F / 4 + 255) / 256;   // 12500

    for (int layer = 0; layer < 2; ++layer) {
        const float* X   = layer ? px : x;
        const int    K   = layer ? 256 : 128;
        const float* W   = layer ? W2 : W1;
        const float* as_ = layer ? as2 : as1;
        const float* ad_ = layer ? ad2 : ad1;
        const float* b_  = layer ? b2 : b1;

        sgemm_kernel<<<gemm_grid, 256>>>(X, W, ph, N_NODES, K);
        node_prep_kernel<<<NWB, 256>>>(as_, ad_);
        edge_agg_kernel<<<EWB, 256>>>(ei);
        node_out_kernel<<<XOB, 256>>>(b_);
    }
    mlp_pred_tc<<<N_EDGES / 64, 128>>>(ei, ea, px,
                                       Wm1, bm1, Wm2, bm2,
                                       Wp1, bp1, Wp2, bp2, out);
}

// round 3
// speedup vs baseline: 1.6473x; 1.5013x over previous
#include <cuda_runtime.h>
#include <math.h>

#define N_NODES 50000
#define N_EDGES 400000
#define HEADS 8
#define HID 32
#define F 256            // HEADS*HID
#define NEG 0.2f

// ---------------- scratch (device globals: allocation-free) ----------------
__device__ float g_h[N_NODES * F];        // X @ W (pre-attention features)
__device__ float g_agg[N_NODES * F];      // unnormalized weighted sum
__device__ float g_x[N_NODES * F];        // relu(agg/denom + b)
__device__ float g_asrc[N_NODES * HEADS];
__device__ float g_adst[N_NODES * HEADS];
__device__ float g_denom[N_NODES * HEADS];
__device__ float g_p[N_NODES * 64];       // [P_a | P_b] node projections
__device__ float g_wcat[256 * 64];        // [Wp1_a | Wp1_b] packed

__device__ __forceinline__ float leaky(float x) { return x > 0.f ? x : NEG * x; }

// ---------------- SGEMM: C[M x N] = A[M x K] @ B[K x N] -------------------
// 128x64 tile, BK=16, 256 threads, 8x4 micro-tile. N tiles via blockIdx.y.
__global__ __launch_bounds__(256) void sgemm_kernel(
    const float* __restrict__ A, const float* __restrict__ B,
    float* __restrict__ C, int M, int K, int ldb, int ldc)
{
    __shared__ float As[16][128];
    __shared__ float Bs[16][64];
    const int tid = threadIdx.x;
    const int tx = tid & 15;
    const int ty = tid >> 4;
    const int m0 = blockIdx.x * 128;
    const int n0 = blockIdx.y * 64;

    float acc[8][4];
#pragma unroll
    for (int i = 0; i < 8; ++i)
#pragma unroll
        for (int j = 0; j < 4; ++j) acc[i][j] = 0.f;

    for (int k0 = 0; k0 < K; k0 += 16) {
#pragma unroll
        for (int jj = 0; jj < 2; ++jj) {
            int f = tid + jj * 256;
            int m = f >> 2;
            int kq = (f & 3) * 4;
            float4 v = make_float4(0.f, 0.f, 0.f, 0.f);
            if (m0 + m < M)
                v = *(const float4*)&A[(size_t)(m0 + m) * K + k0 + kq];
            As[kq + 0][m] = v.x; As[kq + 1][m] = v.y;
            As[kq + 2][m] = v.z; As[kq + 3][m] = v.w;
        }
        {
            int kk = tid >> 4;
            int nq = (tid & 15) * 4;
            *(float4*)&Bs[kk][nq] = *(const float4*)&B[(size_t)(k0 + kk) * ldb + n0 + nq];
        }
        __syncthreads();
#pragma unroll
        for (int kk = 0; kk < 16; ++kk) {
            float4 b4 = *(float4*)&Bs[kk][tx * 4];
            float4 a0 = *(float4*)&As[kk][ty * 8];
            float4 a1 = *(float4*)&As[kk][ty * 8 + 4];
            float a[8] = {a0.x, a0.y, a0.z, a0.w, a1.x, a1.y, a1.z, a1.w};
#pragma unroll
            for (int i = 0; i < 8; ++i) {
                acc[i][0] += a[i] * b4.x; acc[i][1] += a[i] * b4.y;
                acc[i][2] += a[i] * b4.z; acc[i][3] += a[i] * b4.w;
            }
        }
        __syncthreads();
    }
#pragma unroll
    for (int i = 0; i < 8; ++i) {
        int m = m0 + ty * 8 + i;
        if (m < M)
            *(float4*)&C[(size_t)m * ldc + n0 + tx * 4] =
                make_float4(acc[i][0], acc[i][1], acc[i][2], acc[i][3]);
    }
}

// ------- node prep: alpha_src/dst + self-loop weight + agg/denom init ------
// one warp per node, single pass over g_h (float4), 8-lane segment reduce
__global__ __launch_bounds__(256) void node_prep_kernel(
    const float* __restrict__ a_src, const float* __restrict__ a_dst)
{
    __shared__ float sA[256], sD[256];
    const int tid = threadIdx.x;
    sA[tid] = a_src[tid];
    sD[tid] = a_dst[tid];
    __syncthreads();
    const int warp = tid >> 5, lane = tid & 31;
    const int n = blockIdx.x * 8 + warp;
    if (n >= N_NODES) return;

    const int head0 = lane >> 3;              // head of v0 cols; v1 head = head0+4
    float4 v0 = *(float4*)&g_h[(size_t)n * 256 + lane * 4];
    float4 v1 = *(float4*)&g_h[(size_t)n * 256 + 128 + lane * 4];
    float4 a0 = *(float4*)&sA[lane * 4];
    float4 a1 = *(float4*)&sA[128 + lane * 4];
    float4 d0 = *(float4*)&sD[lane * 4];
    float4 d1 = *(float4*)&sD[128 + lane * 4];

    float ps0 = v0.x * a0.x + v0.y * a0.y + v0.z * a0.z + v0.w * a0.w;
    float pd0 = v0.x * d0.x + v0.y * d0.y + v0.z * d0.z + v0.w * d0.w;
    float ps1 = v1.x * a1.x + v1.y * a1.y + v1.z * a1.z + v1.w * a1.w;
    float pd1 = v1.x * d1.x + v1.y * d1.y + v1.z * d1.z + v1.w * d1.w;
#pragma unroll
    for (int off = 4; off; off >>= 1) {
        ps0 += __shfl_xor_sync(0xffffffffu, ps0, off);
        pd0 += __shfl_xor_sync(0xffffffffu, pd0, off);
        ps1 += __shfl_xor_sync(0xffffffffu, ps1, off);
        pd1 += __shfl_xor_sync(0xffffffffu, pd1, off);
    }
    float w0 = expf(leaky(ps0 + pd0));
    float w1 = expf(leaky(ps1 + pd1));
    if ((lane & 7) == 0) {
        g_asrc[n * 8 + head0]     = ps0;  g_asrc[n * 8 + 4 + head0] = ps1;
        g_adst[n * 8 + head0]     = pd0;  g_adst[n * 8 + 4 + head0] = pd1;
        g_denom[n * 8 + head0]    = w0;   g_denom[n * 8 + 4 + head0] = w1;
    }
    v0.x *= w0; v0.y *= w0; v0.z *= w0; v0.w *= w0;
    v1.x *= w1; v1.y *= w1; v1.z *= w1; v1.w *= w1;
    *(float4*)&g_agg[(size_t)n * 256 + lane * 4] = v0;
    *(float4*)&g_agg[(size_t)n * 256 + 128 + lane * 4] = v1;
}

// ---- single fused edge pass: denom += exp(e), agg += exp(e)*h[src] --------
// one warp per edge
__global__ __launch_bounds__(256) void edge_agg_kernel(const int* __restrict__ ei)
{
    const int warp = threadIdx.x >> 5, lane = threadIdx.x & 31;
    const int e = blockIdx.x * 8 + warp;
    if (e >= N_EDGES) return;
    int s = ei[e], d = ei[N_EDGES + e];
    float w = 0.f;
    if (lane < 8) {
        float ee = leaky(g_asrc[s * 8 + lane] + g_adst[d * 8 + lane]);
        w = expf(ee);
        atomicAdd(&g_denom[d * 8 + lane], w);
    }
    float al0 = __shfl_sync(0xffffffffu, w, lane >> 3);
    float al1 = __shfl_sync(0xffffffffu, w, 4 + (lane >> 3));
    float4 v0 = *(const float4*)&g_h[(size_t)s * 256 + lane * 4];
    float4 v1 = *(const float4*)&g_h[(size_t)s * 256 + 128 + lane * 4];
    v0.x *= al0; v0.y *= al0; v0.z *= al0; v0.w *= al0;
    v1.x *= al1; v1.y *= al1; v1.z *= al1; v1.w *= al1;
    atomicAdd((float4*)&g_agg[(size_t)d * 256 + lane * 4], v0);
    atomicAdd((float4*)&g_agg[(size_t)d * 256 + 128 + lane * 4], v1);
}

// ---------------- node: x = relu(agg/denom + b) ----------------
__global__ __launch_bounds__(256) void node_out_kernel(const float* __restrict__ b)
{
    int i = blockIdx.x * blockDim.x + threadIdx.x;      // float4 index
    if (i >= N_NODES * F / 4) return;
    int n = i >> 6;
    int c4 = i & 63;
    int head = c4 >> 3;
    float inv = 1.f / g_denom[n * 8 + head];
    float4 v = *(float4*)&g_agg[(size_t)i * 4];
    float4 bb = *(const float4*)&b[c4 * 4];
    v.x = v.x * inv + bb.x;
    v.y = v.y * inv + bb.y;
    v.z = v.z * inv + bb.z;
    v.w = v.w * inv + bb.w;
    v.x = v.x > 0.f ? v.x : 0.f;
    v.y = v.y > 0.f ? v.y : 0.f;
    v.z = v.z > 0.f ? v.z : 0.f;
    v.w = v.w > 0.f ? v.w : 0.f;
    *(float4*)&g_x[(size_t)i * 4] = v;
}

// ---------------- pack Wcat = [Wp1_a | Wp1_b] : [256 x 64] ----------------
__global__ __launch_bounds__(256) void pack_wcat_kernel(const float* __restrict__ Wp1)
{
    int i = blockIdx.x * blockDim.x + threadIdx.x;
    if (i >= 256 * 64) return;
    int k = i >> 6, j = i & 63;
    g_wcat[i] = (j < 32) ? Wp1[k * 32 + j] : Wp1[(256 + k) * 32 + (j - 32)];
}

// ---------------- edge predictor: emb MLP + combine (fp32) ----------------
// 64 edges/block, 128 threads; tx = col group (4 cols), ey = 4-edge group
__global__ __launch_bounds__(128) void edge_pred_kernel(
    const int* __restrict__ ei, const float* __restrict__ edge_attr,
    const float* __restrict__ Wm1, const float* __restrict__ bm1,
    const float* __restrict__ Wm2, const float* __restrict__ bm2,
    const float* __restrict__ Wp1, const float* __restrict__ bp1,
    const float* __restrict__ Wp2, const float* __restrict__ bp2,
    float* __restrict__ out)
{
    __shared__ float sEA[64 * 33];
    __shared__ float sT1[64 * 33];
    __shared__ float sW[3072];          // Wm1 | Wm2 | Wp1_c
    __shared__ int   sRow[64], sCol[64];
    __shared__ float sB[64];            // bm1 | bm2

    const int tid = threadIdx.x;
    const int tx = tid & 7;
    const int ey = tid >> 3;
    const int e0 = blockIdx.x * 64;

    if (tid < 64) {
        sRow[tid] = ei[e0 + tid];
        sCol[tid] = ei[N_EDGES + e0 + tid];
    }
    for (int i = tid; i < 3072; i += 128)
        sW[i] = (i < 1024) ? Wm1[i]
              : (i < 2048) ? Wm2[i - 1024]
                           : Wp1[512 * 32 + (i - 2048)];
    if (tid < 32) { sB[tid] = bm1[tid]; sB[32 + tid] = bm2[tid]; }
    for (int f = tid; f < 64 * 8; f += 128) {
        int e = f >> 3, q = f & 7;
        float4 v = *(const float4*)&edge_attr[(size_t)(e0 + e) * 32 + q * 4];
        float* p = &sEA[e * 33 + q * 4];
        p[0] = v.x; p[1] = v.y; p[2] = v.z; p[3] = v.w;
    }
    __syncthreads();

    // layer 1: T1 = relu(EA @ Wm1 + bm1)
    {
        float acc[4][4];
#pragma unroll
        for (int i = 0; i < 4; ++i)
#pragma unroll
            for (int j = 0; j < 4; ++j) acc[i][j] = 0.f;
#pragma unroll
        for (int k = 0; k < 32; ++k) {
            float4 w = *(const float4*)&sW[k * 32 + tx * 4];
#pragma unroll
            for (int i = 0; i < 4; ++i) {
                float a = sEA[(ey * 4 + i) * 33 + k];
                acc[i][0] += a * w.x; acc[i][1] += a * w.y;
                acc[i][2] += a * w.z; acc[i][3] += a * w.w;
            }
        }
#pragma unroll
        for (int i = 0; i < 4; ++i)
#pragma unroll
            for (int j = 0; j < 4; ++j) {
                float v = acc[i][j] + sB[tx * 4 + j];
                sT1[(ey * 4 + i) * 33 + tx * 4 + j] = v > 0.f ? v : 0.f;
            }
    }
    __syncthreads();
    // layer 2: EMB = relu(T1 @ Wm2 + bm2) -> sEA (reuse)
    {
        float acc[4][4];
#pragma unroll
        for (int i = 0; i < 4; ++i)
#pragma unroll
            for (int j = 0; j < 4; ++j) acc[i][j] = 0.f;
#pragma unroll
        for (int k = 0; k < 32; ++k) {
            float4 w = *(const float4*)&sW[1024 + k * 32 + tx * 4];
#pragma unroll
            for (int i = 0; i < 4; ++i) {
                float a = sT1[(ey * 4 + i) * 33 + k];
                acc[i][0] += a * w.x; acc[i][1] += a * w.y;
                acc[i][2] += a * w.z; acc[i][3] += a * w.w;
            }
        }
        __syncthreads();
#pragma unroll
        for (int i = 0; i < 4; ++i)
#pragma unroll
            for (int j = 0; j < 4; ++j) {
                float v = acc[i][j] + sB[32 + tx * 4 + j];
                sEA[(ey * 4 + i) * 33 + tx * 4 + j] = v > 0.f ? v : 0.f;
            }
    }
    __syncthreads();
    // layer 3: acc = EMB @ Wp1_c  (emb contribution to pre-activation)
    float acc[4][4];
#pragma unroll
    for (int i = 0; i < 4; ++i)
#pragma unroll
        for (int j = 0; j < 4; ++j) acc[i][j] = 0.f;
#pragma unroll
    for (int k = 0; k < 32; ++k) {
        float4 w = *(const float4*)&sW[2048 + k * 32 + tx * 4];
#pragma unroll
        for (int i = 0; i < 4; ++i) {
            float a = sEA[(ey * 4 + i) * 33 + k];
            acc[i][0] += a * w.x; acc[i][1] += a * w.y;
            acc[i][2] += a * w.z; acc[i][3] += a * w.w;
        }
    }

    // epilogue: pre = acc + P_a[row] + P_b[col] + bp1; out = relu(pre)@Wp2 + bp2
    float4 bp = *(const float4*)&bp1[tx * 4];
    float4 wp = *(const float4*)&Wp2[tx * 4];
    float bias2 = bp2[0];
#pragma unroll
    for (int i = 0; i < 4; ++i) {
        int e = ey * 4 + i;
        int r = sRow[e], c = sCol[e];
        float4 pa = *(const float4*)&g_p[(size_t)r * 64 + tx * 4];
        float4 pb = *(const float4*)&g_p[(size_t)c * 64 + 32 + tx * 4];
        float h0 = acc[i][0] + pa.x + pb.x + bp.x; h0 = h0 > 0.f ? h0 : 0.f;
        float h1 = acc[i][1] + pa.y + pb.y + bp.y; h1 = h1 > 0.f ? h1 : 0.f;
        float h2 = acc[i][2] + pa.z + pb.z + bp.z; h2 = h2 > 0.f ? h2 : 0.f;
        float h3 = acc[i][3] + pa.w + pb.w + bp.w; h3 = h3 > 0.f ? h3 : 0.f;
        float p = h0 * wp.x + h1 * wp.y + h2 * wp.z + h3 * wp.w;
        p += __shfl_down_sync(0xffffffffu, p, 4, 8);
        p += __shfl_down_sync(0xffffffffu, p, 2, 8);
        p += __shfl_down_sync(0xffffffffu, p, 1, 8);
        if (tx == 0) out[e0 + e] = p + bias2;
    }
}

// ---------------- host ----------------
extern "C" void kernel_launch(void* const* d_in, const int* in_sizes, int n_in,
                              void* d_out, int out_size)
{
    const float* x   = (const float*)d_in[0];
    const int*   ei  = (const int*)d_in[1];
    const float* ea  = (const float*)d_in[2];
    const float* W1  = (const float*)d_in[3];
    const float* as1 = (const float*)d_in[4];
    const float* ad1 = (const float*)d_in[5];
    const float* b1  = (const float*)d_in[6];
    const float* W2  = (const float*)d_in[7];
    const float* as2 = (const float*)d_in[8];
    const float* ad2 = (const float*)d_in[9];
    const float* b2  = (const float*)d_in[10];
    const float* Wm1 = (const float*)d_in[11];
    const float* bm1 = (const float*)d_in[12];
    const float* Wm2 = (const float*)d_in[13];
    const float* bm2 = (const float*)d_in[14];
    const float* Wp1 = (const float*)d_in[15];
    const float* bp1 = (const float*)d_in[16];
    const float* Wp2 = (const float*)d_in[17];
    const float* bp2 = (const float*)d_in[18];
    float* out = (float*)d_out;

    float *ph = nullptr, *px = nullptr, *pw = nullptr, *pp = nullptr;
    cudaGetSymbolAddress((void**)&ph, g_h);
    cudaGetSymbolAddress((void**)&px, g_x);
    cudaGetSymbolAddress((void**)&pw, g_wcat);
    cudaGetSymbolAddress((void**)&pp, g_p);

    const dim3 gemm_grid(391, 4);
    const int NWB = (N_NODES + 7) / 8;
    const int EWB = (N_EDGES + 7) / 8;
    const int XOB = (N_NODES * F / 4 + 255) / 256;

    for (int layer = 0; layer < 2; ++layer) {
        const float* X   = layer ? px : x;
        const int    K   = layer ? 256 : 128;
        const float* W   = layer ? W2 : W1;
        const float* as_ = layer ? as2 : as1;
        const float* ad_ = layer ? ad2 : ad1;
        const float* b_  = layer ? b2 : b1;

        sgemm_kernel<<<gemm_grid, 256>>>(X, W, ph, N_NODES, K, 256, 256);
        node_prep_kernel<<<NWB, 256>>>(as_, ad_);
        edge_agg_kernel<<<EWB, 256>>>(ei);
        node_out_kernel<<<XOB, 256>>>(b_);
    }
    pack_wcat_kernel<<<64, 256>>>(Wp1);
    sgemm_kernel<<<dim3(391, 1), 256>>>(px, pw, pp, N_NODES, 256, 64, 64);
    edge_pred_kernel<<<N_EDGES / 64, 128>>>(ei, ea,
                                            Wm1, bm1, Wm2, bm2,
                                            Wp1, bp1, Wp2, bp2, out);
}

// round 4
// speedup vs baseline: 2.0385x; 1.2375x over previous
#include <cuda_runtime.h>
#include <math.h>

#define N_NODES 50000
#define N_EDGES 400000
#define HEADS 8
#define HID 32
#define F 256            // HEADS*HID
#define NEG 0.2f

// ---------------- scratch (device globals: allocation-free) ----------------
__device__ float g_h[N_NODES * F];        // X @ W (pre-attention features)
__device__ float g_x[N_NODES * F];        // layer output
__device__ float g_asrc[N_NODES * HEADS];
__device__ float g_adst[N_NODES * HEADS];
__device__ float g_p[N_NODES * 64];       // [P_a | P_b] node projections
__device__ float g_wcat[256 * 64];        // [Wp1_a | Wp1_b] packed
__device__ int   g_cnt[N_NODES];          // in-degree counters
__device__ int   g_off[N_NODES + 1];      // CSR offsets (exclusive)
__device__ int   g_fill[N_NODES];         // scatter cursors
__device__ int   g_bsum[256];             // scan block sums
__device__ int   g_csrc[N_EDGES];         // CSR: src node per in-edge

__device__ __forceinline__ float leaky(float x) { return x > 0.f ? x : NEG * x; }

// ---------------- SGEMM: C[M x N] = A[M x K] @ B[K x N] -------------------
// 128x64 tile, BK=16, 256 threads, 8x4 micro-tile.
// Optional fused epilogue: per-row attention dots for the 2 heads in this tile.
__global__ __launch_bounds__(256) void sgemm_kernel(
    const float* __restrict__ A, const float* __restrict__ B,
    float* __restrict__ C, int M, int K, int ldb, int ldc,
    const float* __restrict__ a_src, const float* __restrict__ a_dst)
{
    __shared__ float As[16][128];
    __shared__ float Bs[16][64];
    __shared__ float sAs[64], sAd[64];
    const int tid = threadIdx.x;
    const int tx = tid & 15;
    const int ty = tid >> 4;
    const int m0 = blockIdx.x * 128;
    const int n0 = blockIdx.y * 64;

    if (a_src != nullptr && tid < 64) {
        sAs[tid] = a_src[n0 + tid];
        sAd[tid] = a_dst[n0 + tid];
    }

    float acc[8][4];
#pragma unroll
    for (int i = 0; i < 8; ++i)
#pragma unroll
        for (int j = 0; j < 4; ++j) acc[i][j] = 0.f;

    for (int k0 = 0; k0 < K; k0 += 16) {
#pragma unroll
        for (int jj = 0; jj < 2; ++jj) {
            int f = tid + jj * 256;
            int m = f >> 2;
            int kq = (f & 3) * 4;
            float4 v = make_float4(0.f, 0.f, 0.f, 0.f);
            if (m0 + m < M)
                v = *(const float4*)&A[(size_t)(m0 + m) * K + k0 + kq];
            As[kq + 0][m] = v.x; As[kq + 1][m] = v.y;
            As[kq + 2][m] = v.z; As[kq + 3][m] = v.w;
        }
        {
            int kk = tid >> 4;
            int nq = (tid & 15) * 4;
            *(float4*)&Bs[kk][nq] = *(const float4*)&B[(size_t)(k0 + kk) * ldb + n0 + nq];
        }
        __syncthreads();
#pragma unroll
        for (int kk = 0; kk < 16; ++kk) {
            float4 b4 = *(float4*)&Bs[kk][tx * 4];
            float4 a0 = *(float4*)&As[kk][ty * 8];
            float4 a1 = *(float4*)&As[kk][ty * 8 + 4];
            float a[8] = {a0.x, a0.y, a0.z, a0.w, a1.x, a1.y, a1.z, a1.w};
#pragma unroll
            for (int i = 0; i < 8; ++i) {
                acc[i][0] += a[i] * b4.x; acc[i][1] += a[i] * b4.y;
                acc[i][2] += a[i] * b4.z; acc[i][3] += a[i] * b4.w;
            }
        }
        __syncthreads();
    }
#pragma unroll
    for (int i = 0; i < 8; ++i) {
        int m = m0 + ty * 8 + i;
        if (m < M)
            *(float4*)&C[(size_t)m * ldc + n0 + tx * 4] =
                make_float4(acc[i][0], acc[i][1], acc[i][2], acc[i][3]);
    }
    if (a_src != nullptr) {
        // per-row dot with a_src/a_dst; 8-lane reduce (tx 0..7 head0, 8..15 head1)
        float4 wa = *(float4*)&sAs[tx * 4];
        float4 wd = *(float4*)&sAd[tx * 4];
#pragma unroll
        for (int i = 0; i < 8; ++i) {
            float ps = acc[i][0] * wa.x + acc[i][1] * wa.y + acc[i][2] * wa.z + acc[i][3] * wa.w;
            float pd = acc[i][0] * wd.x + acc[i][1] * wd.y + acc[i][2] * wd.z + acc[i][3] * wd.w;
            ps += __shfl_down_sync(0xffffffffu, ps, 4, 8);
            ps += __shfl_down_sync(0xffffffffu, ps, 2, 8);
            ps += __shfl_down_sync(0xffffffffu, ps, 1, 8);
            pd += __shfl_down_sync(0xffffffffu, pd, 4, 8);
            pd += __shfl_down_sync(0xffffffffu, pd, 2, 8);
            pd += __shfl_down_sync(0xffffffffu, pd, 1, 8);
            int m = m0 + ty * 8 + i;
            if ((tx & 7) == 0 && m < M) {
                int head = (n0 >> 5) + (tx >> 3);
                g_asrc[m * 8 + head] = ps;
                g_adst[m * 8 + head] = pd;
            }
        }
    }
}

// ---------------- CSR build ----------------
__global__ __launch_bounds__(256) void zero_cnt_kernel()
{
    int i = blockIdx.x * blockDim.x + threadIdx.x;
    if (i < N_NODES) g_cnt[i] = 0;
}
__global__ __launch_bounds__(256) void count_kernel(const int* __restrict__ ei)
{
    int e = blockIdx.x * blockDim.x + threadIdx.x;
    if (e < N_EDGES) atomicAdd(&g_cnt[ei[N_EDGES + e]], 1);
}
__global__ __launch_bounds__(256) void scan1_kernel()
{
    __shared__ int sh[256];
    int i = blockIdx.x * 256 + threadIdx.x;
    int v = (i < N_NODES) ? g_cnt[i] : 0;
    sh[threadIdx.x] = v;
    __syncthreads();
#pragma unroll
    for (int off = 1; off < 256; off <<= 1) {
        int t = 0;
        if (threadIdx.x >= off) t = sh[threadIdx.x - off];
        __syncthreads();
        if (threadIdx.x >= off) sh[threadIdx.x] += t;
        __syncthreads();
    }
    if (i < N_NODES) g_off[i + 1] = sh[threadIdx.x];
    if (threadIdx.x == 255) g_bsum[blockIdx.x] = sh[255];
    if (i == 0) g_off[0] = 0;
}
__global__ __launch_bounds__(256) void scan2_kernel(int nblocks)
{
    __shared__ int sh[256];
    int t = threadIdx.x;
    int v = (t < nblocks) ? g_bsum[t] : 0;
    sh[t] = v;
    __syncthreads();
#pragma unroll
    for (int off = 1; off < 256; off <<= 1) {
        int u = 0;
        if (t >= off) u = sh[t - off];
        __syncthreads();
        if (t >= off) sh[t] += u;
        __syncthreads();
    }
    if (t < nblocks) g_bsum[t] = sh[t] - v;    // exclusive
}
__global__ __launch_bounds__(256) void scan3_kernel()
{
    int i = blockIdx.x * 256 + threadIdx.x;
    if (i < N_NODES) g_off[i + 1] += g_bsum[blockIdx.x];
}
__global__ __launch_bounds__(256) void fillcpy_kernel()
{
    int i = blockIdx.x * blockDim.x + threadIdx.x;
    if (i < N_NODES) g_fill[i] = g_off[i];
}
__global__ __launch_bounds__(256) void scatter_kernel(const int* __restrict__ ei)
{
    int e = blockIdx.x * blockDim.x + threadIdx.x;
    if (e >= N_EDGES) return;
    int s = ei[e], d = ei[N_EDGES + e];
    int pos = atomicAdd(&g_fill[d], 1);
    g_csrc[pos] = s;
}

// -------- gather attention: one warp per node, fused softmax+agg+relu ------
__global__ __launch_bounds__(256) void gat_gather_kernel(const float* __restrict__ b)
{
    const int warp = threadIdx.x >> 5, lane = threadIdx.x & 31;
    const int n = blockIdx.x * 8 + warp;
    if (n >= N_NODES) return;
    const unsigned FULL = 0xffffffffu;
    const int h0 = lane >> 3, h1 = 4 + (lane >> 3);

    float myasrc = 0.f, myadst = 0.f;
    if (lane < 8) {
        myasrc = g_asrc[n * 8 + lane];
        myadst = g_adst[n * 8 + lane];
    }
    float4 acc0 = make_float4(0.f, 0.f, 0.f, 0.f);
    float4 acc1 = make_float4(0.f, 0.f, 0.f, 0.f);
    float denom = 0.f;

    const int beg = g_off[n], end = g_off[n + 1];
    for (int i = beg; i < end; ++i) {
        int s = g_csrc[i];
        float w = 0.f;
        if (lane < 8) {
            w = expf(leaky(g_asrc[s * 8 + lane] + myadst));
            denom += w;
        }
        float al0 = __shfl_sync(FULL, w, h0);
        float al1 = __shfl_sync(FULL, w, h1);
        float4 v0 = *(const float4*)&g_h[(size_t)s * 256 + lane * 4];
        float4 v1 = *(const float4*)&g_h[(size_t)s * 256 + 128 + lane * 4];
        acc0.x += al0 * v0.x; acc0.y += al0 * v0.y;
        acc0.z += al0 * v0.z; acc0.w += al0 * v0.w;
        acc1.x += al1 * v1.x; acc1.y += al1 * v1.y;
        acc1.z += al1 * v1.z; acc1.w += al1 * v1.w;
    }
    // self loop
    {
        float w = 0.f;
        if (lane < 8) {
            w = expf(leaky(myasrc + myadst));
            denom += w;
        }
        float al0 = __shfl_sync(FULL, w, h0);
        float al1 = __shfl_sync(FULL, w, h1);
        float4 v0 = *(const float4*)&g_h[(size_t)n * 256 + lane * 4];
        float4 v1 = *(const float4*)&g_h[(size_t)n * 256 + 128 + lane * 4];
        acc0.x += al0 * v0.x; acc0.y += al0 * v0.y;
        acc0.z += al0 * v0.z; acc0.w += al0 * v0.w;
        acc1.x += al1 * v1.x; acc1.y += al1 * v1.y;
        acc1.z += al1 * v1.z; acc1.w += al1 * v1.w;
    }
    float inv0 = 1.f / __shfl_sync(FULL, denom, h0);
    float inv1 = 1.f / __shfl_sync(FULL, denom, h1);
    float4 bb0 = *(const float4*)&b[lane * 4];
    float4 bb1 = *(const float4*)&b[128 + lane * 4];
    float4 o0, o1;
    o0.x = fmaxf(acc0.x * inv0 + bb0.x, 0.f);
    o0.y = fmaxf(acc0.y * inv0 + bb0.y, 0.f);
    o0.z = fmaxf(acc0.z * inv0 + bb0.z, 0.f);
    o0.w = fmaxf(acc0.w * inv0 + bb0.w, 0.f);
    o1.x = fmaxf(acc1.x * inv1 + bb1.x, 0.f);
    o1.y = fmaxf(acc1.y * inv1 + bb1.y, 0.f);
    o1.z = fmaxf(acc1.z * inv1 + bb1.z, 0.f);
    o1.w = fmaxf(acc1.w * inv1 + bb1.w, 0.f);
    *(float4*)&g_x[(size_t)n * 256 + lane * 4] = o0;
    *(float4*)&g_x[(size_t)n * 256 + 128 + lane * 4] = o1;
}

// ---------------- pack Wcat = [Wp1_a | Wp1_b] : [256 x 64] ----------------
__global__ __launch_bounds__(256) void pack_wcat_kernel(const float* __restrict__ Wp1)
{
    int i = blockIdx.x * blockDim.x + threadIdx.x;
    if (i >= 256 * 64) return;
    int k = i >> 6, j = i & 63;
    g_wcat[i] = (j < 32) ? Wp1[k * 32 + j] : Wp1[(256 + k) * 32 + (j - 32)];
}

// ---------------- edge predictor: emb MLP + combine (fp32) ----------------
__global__ __launch_bounds__(128) void edge_pred_kernel(
    const int* __restrict__ ei, const float* __restrict__ edge_attr,
    const float* __restrict__ Wm1, const float* __restrict__ bm1,
    const float* __restrict__ Wm2, const float* __restrict__ bm2,
    const float* __restrict__ Wp1, const float* __restrict__ bp1,
    const float* __restrict__ Wp2, const float* __restrict__ bp2,
    float* __restrict__ out)
{
    __shared__ float sEA[64 * 33];
    __shared__ float sT1[64 * 33];
    __shared__ float sW[3072];          // Wm1 | Wm2 | Wp1_c
    __shared__ int   sRow[64], sCol[64];
    __shared__ float sB[64];            // bm1 | bm2

    const int tid = threadIdx.x;
    const int tx = tid & 7;
    const int ey = tid >> 3;
    const int e0 = blockIdx.x * 64;

    if (tid < 64) {
        sRow[tid] = ei[e0 + tid];
        sCol[tid] = ei[N_EDGES + e0 + tid];
    }
    for (int i = tid; i < 3072; i += 128)
        sW[i] = (i < 1024) ? Wm1[i]
              : (i < 2048) ? Wm2[i - 1024]
                           : Wp1[512 * 32 + (i - 2048)];
    if (tid < 32) { sB[tid] = bm1[tid]; sB[32 + tid] = bm2[tid]; }
    for (int f = tid; f < 64 * 8; f += 128) {
        int e = f >> 3, q = f & 7;
        float4 v = *(const float4*)&edge_attr[(size_t)(e0 + e) * 32 + q * 4];
        float* p = &sEA[e * 33 + q * 4];
        p[0] = v.x; p[1] = v.y; p[2] = v.z; p[3] = v.w;
    }
    __syncthreads();

    // layer 1: T1 = relu(EA @ Wm1 + bm1)
    {
        float acc[4][4];
#pragma unroll
        for (int i = 0; i < 4; ++i)
#pragma unroll
            for (int j = 0; j < 4; ++j) acc[i][j] = 0.f;
#pragma unroll
        for (int k = 0; k < 32; ++k) {
            float4 w = *(const float4*)&sW[k * 32 + tx * 4];
#pragma unroll
            for (int i = 0; i < 4; ++i) {
                float a = sEA[(ey * 4 + i) * 33 + k];
                acc[i][0] += a * w.x; acc[i][1] += a * w.y;
                acc[i][2] += a * w.z; acc[i][3] += a * w.w;
            }
        }
#pragma unroll
        for (int i = 0; i < 4; ++i)
#pragma unroll
            for (int j = 0; j < 4; ++j) {
                float v = acc[i][j] + sB[tx * 4 + j];
                sT1[(ey * 4 + i) * 33 + tx * 4 + j] = v > 0.f ? v : 0.f;
            }
    }
    __syncthreads();
    // layer 2: EMB = relu(T1 @ Wm2 + bm2) -> sEA (reuse)
    {
        float acc[4][4];
#pragma unroll
        for (int i = 0; i < 4; ++i)
#pragma unroll
            for (int j = 0; j < 4; ++j) acc[i][j] = 0.f;
#pragma unroll
        for (int k = 0; k < 32; ++k) {
            float4 w = *(const float4*)&sW[1024 + k * 32 + tx * 4];
#pragma unroll
            for (int i = 0; i < 4; ++i) {
                float a = sT1[(ey * 4 + i) * 33 + k];
                acc[i][0] += a * w.x; acc[i][1] += a * w.y;
                acc[i][2] += a * w.z; acc[i][3] += a * w.w;
            }
        }
        __syncthreads();
#pragma unroll
        for (int i = 0; i < 4; ++i)
#pragma unroll
            for (int j = 0; j < 4; ++j) {
                float v = acc[i][j] + sB[32 + tx * 4 + j];
                sEA[(ey * 4 + i) * 33 + tx * 4 + j] = v > 0.f ? v : 0.f;
            }
    }
    __syncthreads();
    // layer 3: acc = EMB @ Wp1_c
    float acc[4][4];
#pragma unroll
    for (int i = 0; i < 4; ++i)
#pragma unroll
        for (int j = 0; j < 4; ++j) acc[i][j] = 0.f;
#pragma unroll
    for (int k = 0; k < 32; ++k) {
        float4 w = *(const float4*)&sW[2048 + k * 32 + tx * 4];
#pragma unroll
        for (int i = 0; i < 4; ++i) {
            float a = sEA[(ey * 4 + i) * 33 + k];
            acc[i][0] += a * w.x; acc[i][1] += a * w.y;
            acc[i][2] += a * w.z; acc[i][3] += a * w.w;
        }
    }

    // epilogue: pre = acc + P_a[row] + P_b[col] + bp1; out = relu(pre)@Wp2 + bp2
    float4 bp = *(const float4*)&bp1[tx * 4];
    float4 wp = *(const float4*)&Wp2[tx * 4];
    float bias2 = bp2[0];
#pragma unroll
    for (int i = 0; i < 4; ++i) {
        int e = ey * 4 + i;
        int r = sRow[e], c = sCol[e];
        float4 pa = *(const float4*)&g_p[(size_t)r * 64 + tx * 4];
        float4 pb = *(const float4*)&g_p[(size_t)c * 64 + 32 + tx * 4];
        float h0 = acc[i][0] + pa.x + pb.x + bp.x; h0 = h0 > 0.f ? h0 : 0.f;
        float h1 = acc[i][1] + pa.y + pb.y + bp.y; h1 = h1 > 0.f ? h1 : 0.f;
        float h2 = acc[i][2] + pa.z + pb.z + bp.z; h2 = h2 > 0.f ? h2 : 0.f;
        float h3 = acc[i][3] + pa.w + pb.w + bp.w; h3 = h3 > 0.f ? h3 : 0.f;
        float p = h0 * wp.x + h1 * wp.y + h2 * wp.z + h3 * wp.w;
        p += __shfl_down_sync(0xffffffffu, p, 4, 8);
        p += __shfl_down_sync(0xffffffffu, p, 2, 8);
        p += __shfl_down_sync(0xffffffffu, p, 1, 8);
        if (tx == 0) out[e0 + e] = p + bias2;
    }
}

// ---------------- host ----------------
extern "C" void kernel_launch(void* const* d_in, const int* in_sizes, int n_in,
                              void* d_out, int out_size)
{
    const float* x   = (const float*)d_in[0];
    const int*   ei  = (const int*)d_in[1];
    const float* ea  = (const float*)d_in[2];
    const float* W1  = (const float*)d_in[3];
    const float* as1 = (const float*)d_in[4];
    const float* ad1 = (const float*)d_in[5];
    const float* b1  = (const float*)d_in[6];
    const float* W2  = (const float*)d_in[7];
    const float* as2 = (const float*)d_in[8];
    const float* ad2 = (const float*)d_in[9];
    const float* b2  = (const float*)d_in[10];
    const float* Wm1 = (const float*)d_in[11];
    const float* bm1 = (const float*)d_in[12];
    const float* Wm2 = (const float*)d_in[13];
    const float* bm2 = (const float*)d_in[14];
    const float* Wp1 = (const float*)d_in[15];
    const float* bp1 = (const float*)d_in[16];
    const float* Wp2 = (const float*)d_in[17];
    const float* bp2 = (const float*)d_in[18];
    float* out = (float*)d_out;

    float *ph = nullptr, *px = nullptr, *pw = nullptr, *pp = nullptr;
    cudaGetSymbolAddress((void**)&ph, g_h);
    cudaGetSymbolAddress((void**)&px, g_x);
    cudaGetSymbolAddress((void**)&pw, g_wcat);
    cudaGetSymbolAddress((void**)&pp, g_p);

    const dim3 gemm_grid(391, 4);
    const int EB  = (N_EDGES + 255) / 256;     // 1563
    const int NB  = (N_NODES + 255) / 256;     // 196
    const int NWB = (N_NODES + 7) / 8;         // 6250

    // ---- CSR build (once; reused by both layers) ----
    zero_cnt_kernel<<<NB, 256>>>();
    count_kernel<<<EB, 256>>>(ei);
    scan1_kernel<<<NB, 256>>>();
    scan2_kernel<<<1, 256>>>(NB);
    scan3_kernel<<<NB, 256>>>();
    fillcpy_kernel<<<NB, 256>>>();
    scatter_kernel<<<EB, 256>>>(ei);

    for (int layer = 0; layer < 2; ++layer) {
        const float* X   = layer ? px : x;
        const int    K   = layer ? 256 : 128;
        const float* W   = layer ? W2 : W1;
        const float* as_ = layer ? as2 : as1;
        const float* ad_ = layer ? ad2 : ad1;
        const float* b_  = layer ? b2 : b1;

        sgemm_kernel<<<gemm_grid, 256>>>(X, W, ph, N_NODES, K, 256, 256, as_, ad_);
        gat_gather_kernel<<<NWB, 256>>>(b_);
    }
    pack_wcat_kernel<<<64, 256>>>(Wp1);
    sgemm_kernel<<<dim3(391, 1), 256>>>(px, pw, pp, N_NODES, 256, 64, 64,
                                        nullptr, nullptr);
    edge_pred_kernel<<<N_EDGES / 64, 128>>>(ei, ea,
                                            Wm1, bm1, Wm2, bm2,
                                            Wp1, bp1, Wp2, bp2, out);
}